// round 1
// baseline (speedup 1.0000x reference)
#include <cuda_runtime.h>
#include <cuda_bf16.h>

#define Bb 128
#define Hh 8
#define Mm 196
#define Dd 128
#define MIDe 64
#define DVv 128

// ---------- f32x2 helpers ----------
__device__ __forceinline__ unsigned long long dupf(float x) {
    unsigned u = __float_as_uint(x);
    unsigned long long r;
    asm("mov.b64 %0, {%1, %1};" : "=l"(r) : "r"(u));
    return r;
}
__device__ __forceinline__ void fma2(unsigned long long& d, unsigned long long a, unsigned long long b) {
    asm("fma.rn.f32x2 %0, %1, %2, %0;" : "+l"(d) : "l"(a), "l"(b));
}
__device__ __forceinline__ float2 unpk(unsigned long long v) {
    unsigned lo, hi;
    asm("mov.b64 {%0, %1}, %2;" : "=r"(lo), "=r"(hi) : "l"(v));
    return make_float2(__uint_as_float(lo), __uint_as_float(hi));
}
__device__ __forceinline__ void lds2u64(unsigned long long& a, unsigned long long& b, const float* p) {
    unsigned s = (unsigned)__cvta_generic_to_shared(p);
    asm("ld.shared.v2.u64 {%0, %1}, [%2];" : "=l"(a), "=l"(b) : "r"(s));
}

struct __align__(16) Smem {
    float qs[128];
    float Wq[128 * 64];      // [d][e]
    float ktile[128 * 128];  // [m][d]
    float Ws[64];
    float bb[64];
    float maskv[256];        // zero beyond 195
    float logits[200];
    float wts[200];
    float pool_p[32 * 64];   // [my][e]
    float pool[64];
    float v2p[2 * 128];
    float red[32];
    float cnt, mx, Z, pad;
};

__global__ __launch_bounds__(256, 2)
void scatt_kernel(const float* __restrict__ qg, const float* __restrict__ keyg_all,
                  const float* __restrict__ maskg, const float* __restrict__ v1g,
                  const float* __restrict__ v2g_all, const float* __restrict__ Wbg,
                  const float* __restrict__ bbg, const float* __restrict__ Wsg,
                  const float* __restrict__ bsg, const float* __restrict__ Wcg,
                  const float* __restrict__ bcg, float* __restrict__ outg)
{
    extern __shared__ float smem_raw[];
    Smem* S = (Smem*)smem_raw;

    const int bh = blockIdx.x;
    const int b = bh >> 3;
    const int tid = threadIdx.x;
    const int lane = tid & 31;
    const int wid = tid >> 5;

    const float* keyg = keyg_all + (size_t)bh * Mm * Dd;
    const float* v2row = v2g_all + (size_t)bh * Mm * DVv;

    // ---- phase 0: small loads ----
    if (tid == 0) S->cnt = 0.f;
    if (tid < 128) S->qs[tid] = qg[bh * 128 + tid];
    if (tid < 64) { S->Ws[tid] = Wsg[tid]; S->bb[tid] = bbg[tid]; }
    S->maskv[tid] = 0.f;
    __syncthreads();

    if (tid < Mm) {
        float mv = maskg[b * Mm + tid];
        S->maskv[tid] = mv;
        atomicAdd(&S->cnt, mv);
    }
    // Wq[d][e] = q[d] * W_basic[d][e]
    #pragma unroll 4
    for (int idx = tid; idx < 128 * 64; idx += 256) {
        int d = idx >> 6;
        S->Wq[idx] = S->qs[d] * Wbg[idx];
    }

    const int ex = tid & 7;       // 8 e-groups of 8
    const int my = tid >> 3;      // 32 m-groups of 4
    const int eb = ex * 8;

    float poolth[8] = {0, 0, 0, 0, 0, 0, 0, 0};

    // ---- stage B: two 128-row tiles ----
    for (int tile = 0; tile < 2; ++tile) {
        const int m0 = tile * 128;
        const int rows = (Mm - m0 < 128) ? (Mm - m0) : 128;

        __syncthreads();
        // load key tile (float4), zero-fill padding rows
        const float4* kg4 = (const float4*)keyg + m0 * 32;
        const int tot4 = rows * 32;
        #pragma unroll
        for (int i4 = tid; i4 < 128 * 32; i4 += 256) {
            float4 v = make_float4(0.f, 0.f, 0.f, 0.f);
            if (i4 < tot4) v = kg4[i4];
            *(float4*)(S->ktile + i4 * 4) = v;
        }
        __syncthreads();

        // warp-uniform skip of fully-padded warps
        if (((my >> 2) << 4) < rows) {
            unsigned long long acc[4][4];
            #pragma unroll
            for (int i = 0; i < 4; i++)
                #pragma unroll
                for (int j = 0; j < 4; j++) acc[i][j] = 0ull;

            const float* k0p = S->ktile + (my * 4) * 128;
            const float* wqp = S->Wq + eb;

            #pragma unroll 4
            for (int d = 0; d < 128; ++d) {
                unsigned long long w0, w1, w2, w3;
                lds2u64(w0, w1, wqp);
                lds2u64(w2, w3, wqp + 4);
                wqp += 64;
                unsigned long long k0 = dupf(k0p[d]);
                unsigned long long k1 = dupf(k0p[d + 128]);
                unsigned long long k2 = dupf(k0p[d + 256]);
                unsigned long long k3 = dupf(k0p[d + 384]);
                fma2(acc[0][0], k0, w0); fma2(acc[0][1], k0, w1);
                fma2(acc[0][2], k0, w2); fma2(acc[0][3], k0, w3);
                fma2(acc[1][0], k1, w0); fma2(acc[1][1], k1, w1);
                fma2(acc[1][2], k1, w2); fma2(acc[1][3], k1, w3);
                fma2(acc[2][0], k2, w0); fma2(acc[2][1], k2, w1);
                fma2(acc[2][2], k2, w2); fma2(acc[2][3], k2, w3);
                fma2(acc[3][0], k3, w0); fma2(acc[3][1], k3, w1);
                fma2(acc[3][2], k3, w2); fma2(acc[3][3], k3, w3);
            }

            // epilogue: relu + bias, pool partials, spatial logits
            float lg[4];
            #pragma unroll
            for (int i = 0; i < 4; i++) {
                const int m = m0 + my * 4 + i;       // <= 210 < 256, maskv padded 0
                const float mk = S->maskv[m];
                float l = 0.f;
                #pragma unroll
                for (int j = 0; j < 4; j++) {
                    float2 hp = unpk(acc[i][j]);
                    float h0 = fmaxf(hp.x + S->bb[eb + 2 * j], 0.f);
                    float h1 = fmaxf(hp.y + S->bb[eb + 2 * j + 1], 0.f);
                    l += h0 * S->Ws[eb + 2 * j] + h1 * S->Ws[eb + 2 * j + 1];
                    poolth[2 * j]     += mk * h0;
                    poolth[2 * j + 1] += mk * h1;
                }
                lg[i] = l;
            }
            #pragma unroll
            for (int i = 0; i < 4; i++) {
                float v = lg[i];
                v += __shfl_down_sync(0xffffffffu, v, 4, 8);
                v += __shfl_down_sync(0xffffffffu, v, 2, 8);
                v += __shfl_down_sync(0xffffffffu, v, 1, 8);
                if (ex == 0) {
                    int m = m0 + my * 4 + i;
                    if (m < Mm) S->logits[m] = v;
                }
            }
        }
    }

    // ---- pool reduction ----
    #pragma unroll
    for (int t = 0; t < 8; t++) S->pool_p[my * 64 + eb + t] = poolth[t];
    __syncthreads();
    if (tid < 64) {
        float s = 0.f;
        #pragma unroll 8
        for (int g = 0; g < 32; g++) s += S->pool_p[g * 64 + tid];
        S->pool[tid] = s / S->cnt;
    }

    // ---- softmax over 196 masked logits ----
    const float bsp = bsg[0];
    float lv = -1e30f;
    if (tid < Mm) lv = (S->maskv[tid] == 0.f) ? -1e9f : (S->logits[tid] + bsp);

    float v = lv;
    #pragma unroll
    for (int off = 16; off > 0; off >>= 1) v = fmaxf(v, __shfl_xor_sync(0xffffffffu, v, off));
    if (lane == 0) S->red[wid] = v;
    __syncthreads();
    float mx = S->red[0];
    #pragma unroll
    for (int i = 1; i < 8; i++) mx = fmaxf(mx, S->red[i]);
    __syncthreads();

    float w = 0.f;
    if (tid < Mm) { w = __expf(lv - mx); S->wts[tid] = w; }
    float sw = w;
    #pragma unroll
    for (int off = 16; off > 0; off >>= 1) sw += __shfl_xor_sync(0xffffffffu, sw, off);
    if (lane == 0) S->red[wid] = sw;
    __syncthreads();
    float Z = 0.f;
    #pragma unroll
    for (int i = 0; i < 8; i++) Z += S->red[i];
    __syncthreads();   // logits/wts ready for all

    // ---- v2 = sum_m alpha[m] * value2[m, :] ----
    const int vv = tid & 127;
    const int hf = tid >> 7;
    float a = 0.f;
    #pragma unroll 7
    for (int m = hf; m < Mm; m += 2) a += S->wts[m] * v2row[m * 128 + vv];
    S->v2p[hf * 128 + vv] = a;
    __syncthreads();

    if (tid < 128) {
        float v2v = (S->v2p[vv] + S->v2p[128 + vv]) / Z;
        float s = 0.f;
        #pragma unroll 8
        for (int e = 0; e < 64; e++) s += S->pool[e] * Wcg[e * 128 + vv];
        float ac = 1.f / (1.f + __expf(-(s + bcg[vv])));
        outg[bh * 128 + vv] = v1g[bh * 128 + vv] * v2v * ac;
    }
}

extern "C" void kernel_launch(void* const* d_in, const int* in_sizes, int n_in,
                              void* d_out, int out_size) {
    const float* q   = (const float*)d_in[0];
    const float* key = (const float*)d_in[1];
    const float* msk = (const float*)d_in[2];
    const float* v1  = (const float*)d_in[3];
    const float* v2  = (const float*)d_in[4];
    const float* Wb  = (const float*)d_in[5];
    const float* bb  = (const float*)d_in[6];
    const float* Ws  = (const float*)d_in[7];
    const float* bs  = (const float*)d_in[8];
    const float* Wc  = (const float*)d_in[9];
    const float* bc  = (const float*)d_in[10];
    float* out = (float*)d_out;

    cudaFuncSetAttribute(scatt_kernel, cudaFuncAttributeMaxDynamicSharedMemorySize,
                         (int)sizeof(Smem));
    scatt_kernel<<<Bb * Hh, 256, sizeof(Smem)>>>(q, key, msk, v1, v2, Wb, bb, Ws, bs, Wc, bc, out);
}

// round 2
// speedup vs baseline: 1.0598x; 1.0598x over previous
#include <cuda_runtime.h>
#include <cuda_bf16.h>

#define Bb 128
#define Hh 8
#define Mm 196
#define Dd 128
#define MIDe 64
#define DVv 128

// ---------- f32x2 helpers ----------
__device__ __forceinline__ unsigned long long dupf(float x) {
    unsigned u = __float_as_uint(x);
    unsigned long long r;
    asm("mov.b64 %0, {%1, %1};" : "=l"(r) : "r"(u));
    return r;
}
__device__ __forceinline__ void fma2(unsigned long long& d, unsigned long long a, unsigned long long b) {
    asm("fma.rn.f32x2 %0, %1, %2, %0;" : "+l"(d) : "l"(a), "l"(b));
}
__device__ __forceinline__ float2 unpk(unsigned long long v) {
    unsigned lo, hi;
    asm("mov.b64 {%0, %1}, %2;" : "=r"(lo), "=r"(hi) : "l"(v));
    return make_float2(__uint_as_float(lo), __uint_as_float(hi));
}
__device__ __forceinline__ void lds2u64(unsigned long long& a, unsigned long long& b, const float* p) {
    unsigned s = (unsigned)__cvta_generic_to_shared(p);
    asm("ld.shared.v2.u64 {%0, %1}, [%2];" : "=l"(a), "=l"(b) : "r"(s));
}

struct __align__(16) Smem {
    float qs[128];
    float Wq[128 * 64];      // [d][e]
    float ktile[128 * 128];  // [m][d], chunk-swizzled: chunk c stored at c ^ ((m>>2)&7)
    float Ws[64];
    float bb[64];
    float maskv[256];        // zero beyond 195
    float logits[200];
    float wts[200];
    float pool_p[32 * 64];   // [my][e]
    float pool[64];
    float v2p[2 * 128];
    float red[32];
    float cnt, mx, Z, pad;
};

__global__ __launch_bounds__(256, 2)
void scatt_kernel(const float* __restrict__ qg, const float* __restrict__ keyg_all,
                  const float* __restrict__ maskg, const float* __restrict__ v1g,
                  const float* __restrict__ v2g_all, const float* __restrict__ Wbg,
                  const float* __restrict__ bbg, const float* __restrict__ Wsg,
                  const float* __restrict__ bsg, const float* __restrict__ Wcg,
                  const float* __restrict__ bcg, float* __restrict__ outg)
{
    extern __shared__ float smem_raw[];
    Smem* S = (Smem*)smem_raw;

    const int bh = blockIdx.x;
    const int b = bh >> 3;
    const int tid = threadIdx.x;
    const int lane = tid & 31;
    const int wid = tid >> 5;

    const float* keyg = keyg_all + (size_t)bh * Mm * Dd;
    const float* v2row = v2g_all + (size_t)bh * Mm * DVv;

    // ---- phase 0: small loads ----
    if (tid == 0) S->cnt = 0.f;
    if (tid < 128) S->qs[tid] = qg[bh * 128 + tid];
    if (tid < 64) { S->Ws[tid] = Wsg[tid]; S->bb[tid] = bbg[tid]; }
    S->maskv[tid] = 0.f;
    __syncthreads();

    if (tid < Mm) {
        float mv = maskg[b * Mm + tid];
        S->maskv[tid] = mv;
        atomicAdd(&S->cnt, mv);
    }
    // Wq[d][e] = q[d] * W_basic[d][e]
    #pragma unroll 4
    for (int idx = tid; idx < 128 * 64; idx += 256) {
        int d = idx >> 6;
        S->Wq[idx] = S->qs[d] * Wbg[idx];
    }

    const int ex = tid & 7;       // 8 e-groups of 8
    const int my = tid >> 3;      // 32 m-groups of 4
    const int eb = ex * 8;
    const int swz = my & 7;       // row>>2 == my for this thread's 4 rows

    float poolth[8] = {0, 0, 0, 0, 0, 0, 0, 0};

    // ---- stage B: two 128-row tiles ----
    for (int tile = 0; tile < 2; ++tile) {
        const int m0 = tile * 128;
        const int rows = (Mm - m0 < 128) ? (Mm - m0) : 128;

        __syncthreads();
        // load key tile (float4), chunk-swizzled store, zero-fill padding rows
        const float4* kg4 = (const float4*)keyg + m0 * 32;
        const int tot4 = rows * 32;
        #pragma unroll
        for (int i4 = tid; i4 < 128 * 32; i4 += 256) {
            float4 v = make_float4(0.f, 0.f, 0.f, 0.f);
            if (i4 < tot4) v = kg4[i4];
            const int row = i4 >> 5;
            const int c = i4 & 31;
            const int cs = c ^ ((row >> 2) & 7);
            *(float4*)(S->ktile + row * 128 + cs * 4) = v;
        }
        __syncthreads();

        // warp-uniform skip of fully-padded warps
        if (((my >> 2) << 4) < rows) {
            unsigned long long acc[4][4];
            #pragma unroll
            for (int i = 0; i < 4; i++)
                #pragma unroll
                for (int j = 0; j < 4; j++) acc[i][j] = 0ull;

            const float* kbase = S->ktile + (my * 4) * 128;
            const float* wqp0 = S->Wq + eb;

            #pragma unroll 4
            for (int dc = 0; dc < 32; ++dc) {
                const int cc = ((dc ^ swz) << 2);
                const float4 ka = *(const float4*)(kbase + cc);
                const float4 kb = *(const float4*)(kbase + 128 + cc);
                const float4 kc = *(const float4*)(kbase + 256 + cc);
                const float4 kd = *(const float4*)(kbase + 384 + cc);
                const float* wqp = wqp0 + dc * 4 * 64;
                #pragma unroll
                for (int t = 0; t < 4; ++t) {
                    unsigned long long w0, w1, w2, w3;
                    lds2u64(w0, w1, wqp);
                    lds2u64(w2, w3, wqp + 4);
                    wqp += 64;
                    unsigned long long k0 = dupf((&ka.x)[t]);
                    unsigned long long k1 = dupf((&kb.x)[t]);
                    unsigned long long k2 = dupf((&kc.x)[t]);
                    unsigned long long k3 = dupf((&kd.x)[t]);
                    fma2(acc[0][0], k0, w0); fma2(acc[0][1], k0, w1);
                    fma2(acc[0][2], k0, w2); fma2(acc[0][3], k0, w3);
                    fma2(acc[1][0], k1, w0); fma2(acc[1][1], k1, w1);
                    fma2(acc[1][2], k1, w2); fma2(acc[1][3], k1, w3);
                    fma2(acc[2][0], k2, w0); fma2(acc[2][1], k2, w1);
                    fma2(acc[2][2], k2, w2); fma2(acc[2][3], k2, w3);
                    fma2(acc[3][0], k3, w0); fma2(acc[3][1], k3, w1);
                    fma2(acc[3][2], k3, w2); fma2(acc[3][3], k3, w3);
                }
            }

            // epilogue: relu + bias, pool partials, spatial logits
            float lg[4];
            #pragma unroll
            for (int i = 0; i < 4; i++) {
                const int m = m0 + my * 4 + i;       // <= 255, maskv padded 0
                const float mk = S->maskv[m];
                float l = 0.f;
                #pragma unroll
                for (int j = 0; j < 4; j++) {
                    float2 hp = unpk(acc[i][j]);
                    float h0 = fmaxf(hp.x + S->bb[eb + 2 * j], 0.f);
                    float h1 = fmaxf(hp.y + S->bb[eb + 2 * j + 1], 0.f);
                    l += h0 * S->Ws[eb + 2 * j] + h1 * S->Ws[eb + 2 * j + 1];
                    poolth[2 * j]     += mk * h0;
                    poolth[2 * j + 1] += mk * h1;
                }
                lg[i] = l;
            }
            #pragma unroll
            for (int i = 0; i < 4; i++) {
                float v = lg[i];
                v += __shfl_down_sync(0xffffffffu, v, 4, 8);
                v += __shfl_down_sync(0xffffffffu, v, 2, 8);
                v += __shfl_down_sync(0xffffffffu, v, 1, 8);
                if (ex == 0) {
                    int m = m0 + my * 4 + i;
                    if (m < Mm) S->logits[m] = v;
                }
            }
        }
    }

    // ---- pool reduction ----
    #pragma unroll
    for (int t = 0; t < 8; t++) S->pool_p[my * 64 + eb + t] = poolth[t];
    __syncthreads();
    if (tid < 64) {
        float s = 0.f;
        #pragma unroll 8
        for (int g = 0; g < 32; g++) s += S->pool_p[g * 64 + tid];
        S->pool[tid] = s / S->cnt;
    }

    // ---- softmax over 196 masked logits ----
    const float bsp = bsg[0];
    float lv = -1e30f;
    if (tid < Mm) lv = (S->maskv[tid] == 0.f) ? -1e9f : (S->logits[tid] + bsp);

    float v = lv;
    #pragma unroll
    for (int off = 16; off > 0; off >>= 1) v = fmaxf(v, __shfl_xor_sync(0xffffffffu, v, off));
    if (lane == 0) S->red[wid] = v;
    __syncthreads();
    float mx = S->red[0];
    #pragma unroll
    for (int i = 1; i < 8; i++) mx = fmaxf(mx, S->red[i]);
    __syncthreads();

    float w = 0.f;
    if (tid < Mm) { w = __expf(lv - mx); S->wts[tid] = w; }
    float sw = w;
    #pragma unroll
    for (int off = 16; off > 0; off >>= 1) sw += __shfl_xor_sync(0xffffffffu, sw, off);
    if (lane == 0) S->red[wid] = sw;
    __syncthreads();
    float Z = 0.f;
    #pragma unroll
    for (int i = 0; i < 8; i++) Z += S->red[i];
    __syncthreads();   // logits/wts ready for all

    // ---- v2 = sum_m alpha[m] * value2[m, :] ----
    const int vv = tid & 127;
    const int hf = tid >> 7;
    float a = 0.f;
    #pragma unroll 7
    for (int m = hf; m < Mm; m += 2) a += S->wts[m] * v2row[m * 128 + vv];
    S->v2p[hf * 128 + vv] = a;
    __syncthreads();

    if (tid < 128) {
        float v2v = (S->v2p[vv] + S->v2p[128 + vv]) / Z;
        float s = 0.f;
        #pragma unroll 8
        for (int e = 0; e < 64; e++) s += S->pool[e] * Wcg[e * 128 + vv];
        float ac = 1.f / (1.f + __expf(-(s + bcg[vv])));
        outg[bh * 128 + vv] = v1g[bh * 128 + vv] * v2v * ac;
    }
}

extern "C" void kernel_launch(void* const* d_in, const int* in_sizes, int n_in,
                              void* d_out, int out_size) {
    const float* q   = (const float*)d_in[0];
    const float* key = (const float*)d_in[1];
    const float* msk = (const float*)d_in[2];
    const float* v1  = (const float*)d_in[3];
    const float* v2  = (const float*)d_in[4];
    const float* Wb  = (const float*)d_in[5];
    const float* bb  = (const float*)d_in[6];
    const float* Ws  = (const float*)d_in[7];
    const float* bs  = (const float*)d_in[8];
    const float* Wc  = (const float*)d_in[9];
    const float* bc  = (const float*)d_in[10];
    float* out = (float*)d_out;

    cudaFuncSetAttribute(scatt_kernel, cudaFuncAttributeMaxDynamicSharedMemorySize,
                         (int)sizeof(Smem));
    scatt_kernel<<<Bb * Hh, 256, sizeof(Smem)>>>(q, key, msk, v1, v2, Wb, bb, Ws, bs, Wc, bc, out);
}

// round 4
// speedup vs baseline: 1.3108x; 1.2369x over previous
#include <cuda_runtime.h>
#include <cuda_fp16.h>
#include <cstdint>

#define Mm 196
#define THREADS 416
#define NWARP 13

// ---- smem byte offsets ----
#define OFF_AHI   0u          // 13*8*32*16 = 53248
#define OFF_ALO   53248u      // 53248
#define OFF_B     106496u     // 8*8*32*16 = 32768  (hi+lo interleaved per lane slot)
#define OFF_STAGE 139264u     // 32768 (Wb staged fp32)
#define OFF_QS    172032u     // 128 f
#define OFF_WS    172544u     // 64 f
#define OFF_BB    172800u     // 64 f
#define OFF_MASK  173056u     // 256 f (zero padded)
#define OFF_LOG   174080u     // 256 f
#define OFF_WTS   175104u     // 256 f
#define OFF_POOLP 176128u     // 13*64 f
#define OFF_POOL  179456u     // 64 f
#define OFF_V2P   179712u     // 3*128 f
#define OFF_RED   181248u     // 16 f
#define OFF_CNT   181312u
#define SMEM_BYTES 181376u

__device__ __forceinline__ void split2(float x, float y, uint32_t& hi, uint32_t& lo) {
    __half hx = __float2half_rn(x), hy = __float2half_rn(y);
    __half lx = __float2half_rn(x - __half2float(hx));
    __half ly = __float2half_rn(y - __half2float(hy));
    hi = ((uint32_t)__half_as_ushort(hy) << 16) | (uint32_t)__half_as_ushort(hx);
    lo = ((uint32_t)__half_as_ushort(ly) << 16) | (uint32_t)__half_as_ushort(lx);
}

__device__ __forceinline__ void mma16816(float* d, uint32_t a0, uint32_t a1, uint32_t a2,
                                         uint32_t a3, uint32_t b0, uint32_t b1) {
    asm volatile(
        "mma.sync.aligned.m16n8k16.row.col.f32.f16.f16.f32 "
        "{%0,%1,%2,%3}, {%4,%5,%6,%7}, {%8,%9}, {%0,%1,%2,%3};"
        : "+f"(d[0]), "+f"(d[1]), "+f"(d[2]), "+f"(d[3])
        : "r"(a0), "r"(a1), "r"(a2), "r"(a3), "r"(b0), "r"(b1));
}

__device__ __forceinline__ void lds128(uint32_t& x, uint32_t& y, uint32_t& z, uint32_t& w,
                                       uint32_t addr) {
    asm volatile("ld.shared.v4.b32 {%0,%1,%2,%3}, [%4];"
                 : "=r"(x), "=r"(y), "=r"(z), "=r"(w) : "r"(addr));
}

__global__ __launch_bounds__(THREADS, 1)
void scatt_hmma(const float* __restrict__ qg, const float* __restrict__ keyg_all,
                const float* __restrict__ maskg, const float* __restrict__ v1g,
                const float* __restrict__ v2g_all, const float* __restrict__ Wbg,
                const float* __restrict__ bbg, const float* __restrict__ Wsg,
                const float* __restrict__ bsg, const float* __restrict__ Wcg,
                const float* __restrict__ bcg, float* __restrict__ outg)
{
    extern __shared__ char sm[];
    const uint32_t smb = (uint32_t)__cvta_generic_to_shared(sm);
    const int tid = threadIdx.x;
    const int lane = tid & 31;
    const int wid = tid >> 5;
    const int bh = blockIdx.x;
    const int b = bh >> 3;

    const float* keyg = keyg_all + (size_t)bh * Mm * 128;
    const float* v2row = v2g_all + (size_t)bh * Mm * 128;

    float* qs    = (float*)(sm + OFF_QS);
    float* wss   = (float*)(sm + OFF_WS);
    float* bbs   = (float*)(sm + OFF_BB);
    float* maskv = (float*)(sm + OFF_MASK);
    float* logits= (float*)(sm + OFF_LOG);
    float* wts   = (float*)(sm + OFF_WTS);
    float* poolp = (float*)(sm + OFF_POOLP);
    float* pool  = (float*)(sm + OFF_POOL);
    float* v2p   = (float*)(sm + OFF_V2P);
    float* red   = (float*)(sm + OFF_RED);
    float* cntp  = (float*)(sm + OFF_CNT);
    float* stage = (float*)(sm + OFF_STAGE);

    // ---- phase 0: stage small tensors + Wb ----
    if (tid == 0) *cntp = 0.f;
    if (tid < 128) qs[tid] = qg[bh * 128 + tid];
    if (tid < 64) { wss[tid] = Wsg[tid]; bbs[tid] = bbg[tid]; }
    if (tid < 256) maskv[tid] = 0.f;
    {
        const float4* wb4 = (const float4*)Wbg;
        for (int i = tid; i < 2048; i += THREADS) ((float4*)stage)[i] = wb4[i];
    }
    __syncthreads();

    if (tid < Mm) {
        float mv = maskg[b * Mm + tid];
        maskv[tid] = mv;
        atomicAdd(cntp, mv);
    }

    // ---- pack B fragments (Wq = q[k]*Wb[k][e], fp16 hi/lo, frag order) ----
    for (int task = tid; task < 512; task += THREADS) {
        const int e = task & 63;
        const int ks = task >> 6;
        const int nt = e >> 3;
        const uint32_t slotbase = (uint32_t)((nt * 8 + ks) * 32);
        #pragma unroll
        for (int t = 0; t < 4; ++t) {
            const int k0 = ks * 16 + t * 2;
            const float x0 = stage[k0 * 64 + e] * qs[k0];
            const float x1 = stage[(k0 + 1) * 64 + e] * qs[k0 + 1];
            const float x2 = stage[(k0 + 8) * 64 + e] * qs[k0 + 8];
            const float x3 = stage[(k0 + 9) * 64 + e] * qs[k0 + 9];
            uint32_t b0h, b0l, b1h, b1l;
            split2(x0, x1, b0h, b0l);
            split2(x2, x3, b1h, b1l);
            const int ln = 4 * (e & 7) + t;
            uint4 val; val.x = b0h; val.y = b1h; val.z = b0l; val.w = b1l;
            *(uint4*)(sm + OFF_B + (slotbase + ln) * 16) = val;
        }
    }

    // ---- pack A fragments (key rows, fp16 hi/lo, frag order, lane^ks skew) ----
    {
        const float4* kg4 = (const float4*)keyg;
        #pragma unroll
        for (int i = 0; i < 16; ++i) {
            const int task = tid + THREADS * i;     // 6656 tasks = 208 rows * 32 quads
            const int row = task >> 5;
            const int q4 = task & 31;
            float4 v = make_float4(0.f, 0.f, 0.f, 0.f);
            if (row < Mm) v = kg4[row * 32 + q4];
            const int mt = row >> 4;
            const int ks = q4 >> 2;
            const int cw = (q4 & 3) * 4;            // 0,4,8,12
            const int t0 = (cw & 4) ? 2 : 0;
            const int reg = ((cw & 8) ? 2 : 0) + ((row >> 3) & 1);
            const int laneb = 4 * (row & 7);
            uint32_t h0, l0, h1, l1;
            split2(v.x, v.y, h0, l0);
            split2(v.z, v.w, h1, l1);
            const uint32_t base = (uint32_t)((mt * 8 + ks) * 32);
            const uint32_t s0 = (base + ((laneb + t0) ^ ks)) * 16 + reg * 4;
            const uint32_t s1 = (base + ((laneb + t0 + 1) ^ ks)) * 16 + reg * 4;
            *(uint32_t*)(sm + OFF_AHI + s0) = h0;
            *(uint32_t*)(sm + OFF_AHI + s1) = h1;
            *(uint32_t*)(sm + OFF_ALO + s0) = l0;
            *(uint32_t*)(sm + OFF_ALO + s1) = l1;
        }
    }
    __syncthreads();

    // ---- MMA mainloop: warp w owns m-tile w (rows 16w..16w+15) ----
    float acc[8][4];
    #pragma unroll
    for (int nt = 0; nt < 8; ++nt)
        #pragma unroll
        for (int r = 0; r < 4; ++r) acc[nt][r] = 0.f;

    #pragma unroll
    for (int ks = 0; ks < 8; ++ks) {
        const uint32_t aoff = (uint32_t)((wid * 8 + ks) * 32 + (lane ^ ks)) * 16;
        uint32_t ah0, ah1, ah2, ah3, al0, al1, al2, al3;
        lds128(ah0, ah1, ah2, ah3, smb + OFF_AHI + aoff);
        lds128(al0, al1, al2, al3, smb + OFF_ALO + aoff);
        #pragma unroll
        for (int nt = 0; nt < 8; ++nt) {
            uint32_t b0h, b1h, b0l, b1l;
            lds128(b0h, b1h, b0l, b1l,
                   smb + OFF_B + (uint32_t)((nt * 8 + ks) * 32 + lane) * 16);
            mma16816(acc[nt], ah0, ah1, ah2, ah3, b0h, b1h);
            mma16816(acc[nt], ah0, ah1, ah2, ah3, b0l, b1l);
            mma16816(acc[nt], al0, al1, al2, al3, b0h, b1h);
        }
    }

    // ---- epilogue: relu+bias -> logits + masked pool ----
    {
        const int g = lane >> 2, t = lane & 3;
        const int r0 = wid * 16 + g, r1 = r0 + 8;
        const float mk0 = maskv[r0], mk1 = maskv[r1];
        float p0 = 0.f, p1 = 0.f;
        #pragma unroll
        for (int nt = 0; nt < 8; ++nt) {
            const int e0 = nt * 8 + t * 2;
            const float ba = bbs[e0], bbv = bbs[e0 + 1];
            const float wa = wss[e0], wbv = wss[e0 + 1];
            float h0 = fmaxf(acc[nt][0] + ba, 0.f);
            float h1 = fmaxf(acc[nt][1] + bbv, 0.f);
            float h2 = fmaxf(acc[nt][2] + ba, 0.f);
            float h3 = fmaxf(acc[nt][3] + bbv, 0.f);
            p0 += h0 * wa + h1 * wbv;
            p1 += h2 * wa + h3 * wbv;
            float pva = mk0 * h0 + mk1 * h2;
            float pvb = mk0 * h1 + mk1 * h3;
            pva += __shfl_xor_sync(0xffffffffu, pva, 4);
            pva += __shfl_xor_sync(0xffffffffu, pva, 8);
            pva += __shfl_xor_sync(0xffffffffu, pva, 16);
            pvb += __shfl_xor_sync(0xffffffffu, pvb, 4);
            pvb += __shfl_xor_sync(0xffffffffu, pvb, 8);
            pvb += __shfl_xor_sync(0xffffffffu, pvb, 16);
            if (g == 0) {
                poolp[wid * 64 + e0] = pva;
                poolp[wid * 64 + e0 + 1] = pvb;
            }
        }
        p0 += __shfl_xor_sync(0xffffffffu, p0, 1);
        p0 += __shfl_xor_sync(0xffffffffu, p0, 2);
        p1 += __shfl_xor_sync(0xffffffffu, p1, 1);
        p1 += __shfl_xor_sync(0xffffffffu, p1, 2);
        if (t == 0) {
            if (r0 < Mm) logits[r0] = p0;
            if (r1 < Mm) logits[r1] = p1;
        }
    }
    __syncthreads();

    // ---- pool reduce ----
    if (tid < 64) {
        float s = 0.f;
        #pragma unroll
        for (int g = 0; g < NWARP; ++g) s += poolp[g * 64 + tid];
        pool[tid] = s / *cntp;
    }

    // ---- softmax over 196 masked logits ----
    const float bsp = bsg[0];
    float lv = -1e30f;
    if (tid < Mm) lv = (maskv[tid] == 0.f) ? -1e9f : (logits[tid] + bsp);

    float v = lv;
    #pragma unroll
    for (int off = 16; off > 0; off >>= 1) v = fmaxf(v, __shfl_xor_sync(0xffffffffu, v, off));
    if (lane == 0) red[wid] = v;
    __syncthreads();
    float mx = red[0];
    #pragma unroll
    for (int i = 1; i < NWARP; ++i) mx = fmaxf(mx, red[i]);
    __syncthreads();

    float w = 0.f;
    if (tid < Mm) { w = __expf(lv - mx); wts[tid] = w; }
    float sw = w;
    #pragma unroll
    for (int off = 16; off > 0; off >>= 1) sw += __shfl_xor_sync(0xffffffffu, sw, off);
    if (lane == 0) red[wid] = sw;
    __syncthreads();
    float Z = 0.f;
    #pragma unroll
    for (int i = 0; i < NWARP; ++i) Z += red[i];
    __syncthreads();

    // ---- v2 = sum_m alpha[m] * value2[m, :] ----
    const int grp = tid >> 7;
    const int vv = tid & 127;
    if (grp < 3) {
        float a = 0.f;
        for (int m = grp; m < Mm; m += 3) a += wts[m] * v2row[m * 128 + vv];
        v2p[grp * 128 + vv] = a;
    }
    __syncthreads();

    if (tid < 128) {
        float v2v = (v2p[vv] + v2p[128 + vv] + v2p[256 + vv]) / Z;
        float s = 0.f;
        #pragma unroll 8
        for (int e = 0; e < 64; ++e) s += pool[e] * Wcg[e * 128 + vv];
        float ac = 1.f / (1.f + __expf(-(s + bcg[vv])));
        outg[bh * 128 + vv] = v1g[bh * 128 + vv] * v2v * ac;
    }
}

extern "C" void kernel_launch(void* const* d_in, const int* in_sizes, int n_in,
                              void* d_out, int out_size) {
    const float* q   = (const float*)d_in[0];
    const float* key = (const float*)d_in[1];
    const float* msk = (const float*)d_in[2];
    const float* v1  = (const float*)d_in[3];
    const float* v2  = (const float*)d_in[4];
    const float* Wb  = (const float*)d_in[5];
    const float* bb  = (const float*)d_in[6];
    const float* Ws  = (const float*)d_in[7];
    const float* bs  = (const float*)d_in[8];
    const float* Wc  = (const float*)d_in[9];
    const float* bc  = (const float*)d_in[10];
    float* out = (float*)d_out;

    cudaFuncSetAttribute(scatt_hmma, cudaFuncAttributeMaxDynamicSharedMemorySize,
                         (int)SMEM_BYTES);
    scatt_hmma<<<128 * 8, THREADS, SMEM_BYTES>>>(q, key, msk, v1, v2, Wb, bb, Ws, bs, Wc, bc, out);
}

// round 5
// speedup vs baseline: 1.8911x; 1.4427x over previous
#include <cuda_runtime.h>
#include <cuda_fp16.h>
#include <cstdint>

#define Mm 196

// ---- kernel1 smem offsets ----
#define K1_B      0u        // 8*8*32*16 = 32768 (B fragments)
#define K1_STAGE  32768u    // 32768 (Wb fp32)
#define K1_QS     65536u    // 128 f
#define K1_WS     66048u    // 64 f
#define K1_BB     66304u    // 64 f
#define K1_MASK   66560u    // 256 f zero-padded
#define K1_POOLP  67584u    // 8*64 f
#define K1_SMEM   69632u

// ---- kernel2 smem offsets ----
#define K2_MASK   0u        // 256 f
#define K2_LOG    1024u     // 256 f
#define K2_WTS    2048u     // 256 f
#define K2_POOL   3072u     // 64 f
#define K2_V2P    3328u     // 4*128 f
#define K2_RED    5376u     // 16 f
#define K2_CNT    5440u
#define K2_SMEM   5504u

__device__ float g_logits[1024 * 196];
__device__ float g_poolp[2048 * 64];

__device__ __forceinline__ void split2(float x, float y, uint32_t& hi, uint32_t& lo) {
    __half hx = __float2half_rn(x), hy = __float2half_rn(y);
    __half lx = __float2half_rn(x - __half2float(hx));
    __half ly = __float2half_rn(y - __half2float(hy));
    hi = ((uint32_t)__half_as_ushort(hy) << 16) | (uint32_t)__half_as_ushort(hx);
    lo = ((uint32_t)__half_as_ushort(ly) << 16) | (uint32_t)__half_as_ushort(lx);
}

__device__ __forceinline__ void mma16816(float* d, uint32_t a0, uint32_t a1, uint32_t a2,
                                         uint32_t a3, uint32_t b0, uint32_t b1) {
    asm volatile(
        "mma.sync.aligned.m16n8k16.row.col.f32.f16.f16.f32 "
        "{%0,%1,%2,%3}, {%4,%5,%6,%7}, {%8,%9}, {%0,%1,%2,%3};"
        : "+f"(d[0]), "+f"(d[1]), "+f"(d[2]), "+f"(d[3])
        : "r"(a0), "r"(a1), "r"(a2), "r"(a3), "r"(b0), "r"(b1));
}

__device__ __forceinline__ void lds128(uint32_t& x, uint32_t& y, uint32_t& z, uint32_t& w,
                                       uint32_t addr) {
    asm volatile("ld.shared.v4.b32 {%0,%1,%2,%3}, [%4];"
                 : "=r"(x), "=r"(y), "=r"(z), "=r"(w) : "r"(addr));
}

// ================= kernel 1: fused GEMM + logits/pool partials =================
__global__ __launch_bounds__(256, 2)
void k1_gemm(const float* __restrict__ qg, const float* __restrict__ keyg_all,
             const float* __restrict__ maskg, const float* __restrict__ Wbg,
             const float* __restrict__ bbg, const float* __restrict__ Wsg)
{
    extern __shared__ char sm[];
    const uint32_t smb = (uint32_t)__cvta_generic_to_shared(sm);
    const int tid = threadIdx.x;
    const int lane = tid & 31;
    const int wid = tid >> 5;
    const int bid = blockIdx.x;
    const int bh = bid >> 1;
    const int half = bid & 1;
    const int b = bh >> 3;
    const int m0 = half * 112;
    const int ntiles = half ? 6 : 7;

    float* qs    = (float*)(sm + K1_QS);
    float* wss   = (float*)(sm + K1_WS);
    float* bbs   = (float*)(sm + K1_BB);
    float* maskv = (float*)(sm + K1_MASK);
    float* poolp = (float*)(sm + K1_POOLP);
    float* stage = (float*)(sm + K1_STAGE);

    // phase 0
    if (tid < 128) qs[tid] = qg[bh * 128 + tid];
    if (tid < 64) { wss[tid] = Wsg[tid]; bbs[tid] = bbg[tid]; }
    maskv[tid] = (tid < Mm) ? maskg[b * Mm + tid] : 0.f;
    {
        const float4* wb4 = (const float4*)Wbg;
        #pragma unroll
        for (int i = tid; i < 2048; i += 256) ((float4*)stage)[i] = wb4[i];
    }
    __syncthreads();

    // pack B fragments: Wq[k][e] = q[k]*Wb[k][e], fp16 hi/lo, mma frag order
    #pragma unroll
    for (int task = tid; task < 512; task += 256) {
        const int e = task & 63;
        const int ks = task >> 6;
        const int nt = e >> 3;
        const uint32_t slotbase = (uint32_t)((nt * 8 + ks) * 32);
        #pragma unroll
        for (int t = 0; t < 4; ++t) {
            const int k0 = ks * 16 + t * 2;
            const float x0 = stage[k0 * 64 + e] * qs[k0];
            const float x1 = stage[(k0 + 1) * 64 + e] * qs[k0 + 1];
            const float x2 = stage[(k0 + 8) * 64 + e] * qs[k0 + 8];
            const float x3 = stage[(k0 + 9) * 64 + e] * qs[k0 + 9];
            uint32_t b0h, b0l, b1h, b1l;
            split2(x0, x1, b0h, b0l);
            split2(x2, x3, b1h, b1l);
            const int ln = 4 * (e & 7) + t;
            uint4 val; val.x = b0h; val.y = b1h; val.z = b0l; val.w = b1l;
            *(uint4*)(sm + K1_B + (slotbase + ln) * 16) = val;
        }
    }
    __syncthreads();

    if (wid < ntiles) {
        float acc[8][4];
        #pragma unroll
        for (int nt = 0; nt < 8; ++nt)
            #pragma unroll
            for (int r = 0; r < 4; ++r) acc[nt][r] = 0.f;

        const float* keyg = keyg_all + (size_t)bh * Mm * 128;
        const int g = lane >> 2, t = lane & 3;
        const int r0 = m0 + wid * 16 + g;
        const int r1 = r0 + 8;
        const int r0c = (r0 < Mm) ? r0 : (Mm - 1);
        const int r1c = (r1 < Mm) ? r1 : (Mm - 1);
        const float2* k0p = (const float2*)(keyg + r0c * 128) + t;
        const float2* k1p = (const float2*)(keyg + r1c * 128) + t;

        float2 n00 = k0p[0], n01 = k0p[4], n10 = k1p[0], n11 = k1p[4];

        #pragma unroll
        for (int ks = 0; ks < 8; ++ks) {
            const float2 c00 = n00, c01 = n01, c10 = n10, c11 = n11;
            if (ks < 7) {
                n00 = k0p[(ks + 1) * 8];
                n01 = k0p[(ks + 1) * 8 + 4];
                n10 = k1p[(ks + 1) * 8];
                n11 = k1p[(ks + 1) * 8 + 4];
            }
            uint32_t a0h, a0l, a1h, a1l, a2h, a2l, a3h, a3l;
            split2(c00.x, c00.y, a0h, a0l);
            split2(c10.x, c10.y, a1h, a1l);
            split2(c01.x, c01.y, a2h, a2l);
            split2(c11.x, c11.y, a3h, a3l);
            #pragma unroll
            for (int nt = 0; nt < 8; ++nt) {
                uint32_t b0h, b1h, b0l, b1l;
                lds128(b0h, b1h, b0l, b1l,
                       smb + K1_B + (uint32_t)((nt * 8 + ks) * 32 + lane) * 16);
                mma16816(acc[nt], a0h, a1h, a2h, a3h, b0h, b1h);
                mma16816(acc[nt], a0h, a1h, a2h, a3h, b0l, b1l);
                mma16816(acc[nt], a0l, a1l, a2l, a3l, b0h, b1h);
            }
        }

        // epilogue: relu+bias -> logit rows + masked pool partials
        const float mk0 = maskv[r0 < 256 ? r0 : 255];
        const float mk1 = maskv[r1 < 256 ? r1 : 255];
        float p0 = 0.f, p1 = 0.f;
        #pragma unroll
        for (int nt = 0; nt < 8; ++nt) {
            const int e0 = nt * 8 + t * 2;
            const float ba = bbs[e0], bbv = bbs[e0 + 1];
            const float wa = wss[e0], wbv = wss[e0 + 1];
            float h0 = fmaxf(acc[nt][0] + ba, 0.f);
            float h1 = fmaxf(acc[nt][1] + bbv, 0.f);
            float h2 = fmaxf(acc[nt][2] + ba, 0.f);
            float h3 = fmaxf(acc[nt][3] + bbv, 0.f);
            p0 += h0 * wa + h1 * wbv;
            p1 += h2 * wa + h3 * wbv;
            float pva = mk0 * h0 + mk1 * h2;
            float pvb = mk0 * h1 + mk1 * h3;
            pva += __shfl_xor_sync(0xffffffffu, pva, 4);
            pva += __shfl_xor_sync(0xffffffffu, pva, 8);
            pva += __shfl_xor_sync(0xffffffffu, pva, 16);
            pvb += __shfl_xor_sync(0xffffffffu, pvb, 4);
            pvb += __shfl_xor_sync(0xffffffffu, pvb, 8);
            pvb += __shfl_xor_sync(0xffffffffu, pvb, 16);
            if (g == 0) {
                poolp[wid * 64 + e0] = pva;
                poolp[wid * 64 + e0 + 1] = pvb;
            }
        }
        p0 += __shfl_xor_sync(0xffffffffu, p0, 1);
        p0 += __shfl_xor_sync(0xffffffffu, p0, 2);
        p1 += __shfl_xor_sync(0xffffffffu, p1, 1);
        p1 += __shfl_xor_sync(0xffffffffu, p1, 2);
        if (t == 0) {
            if (r0 < Mm) g_logits[bh * Mm + r0] = p0;
            if (r1 < Mm) g_logits[bh * Mm + r1] = p1;
        }
    }
    __syncthreads();

    if (tid < 64) {
        float s = 0.f;
        for (int w = 0; w < ntiles; ++w) s += poolp[w * 64 + tid];
        g_poolp[bid * 64 + tid] = s;
    }
}

// ================= kernel 2: softmax + v2 stream + gate =================
__global__ __launch_bounds__(512)
void k2_final(const float* __restrict__ maskg, const float* __restrict__ v1g,
              const float* __restrict__ v2g_all, const float* __restrict__ bsg,
              const float* __restrict__ Wcg, const float* __restrict__ bcg,
              float* __restrict__ outg)
{
    extern __shared__ char sm[];
    const int tid = threadIdx.x;
    const int lane = tid & 31;
    const int wid = tid >> 5;
    const int bh = blockIdx.x;
    const int b = bh >> 3;

    float* maskv  = (float*)(sm + K2_MASK);
    float* logits = (float*)(sm + K2_LOG);
    float* wts    = (float*)(sm + K2_WTS);
    float* pool   = (float*)(sm + K2_POOL);
    float* v2p    = (float*)(sm + K2_V2P);
    float* red    = (float*)(sm + K2_RED);
    float* cntp   = (float*)(sm + K2_CNT);

    if (tid == 0) *cntp = 0.f;
    __syncthreads();

    if (tid < 256) {
        float mv = (tid < Mm) ? maskg[b * Mm + tid] : 0.f;
        maskv[tid] = mv;
        if (tid < Mm) {
            logits[tid] = g_logits[bh * Mm + tid];
            atomicAdd(cntp, mv);
        }
    }
    __syncthreads();

    if (tid < 64)
        pool[tid] = (g_poolp[(bh * 2) * 64 + tid] + g_poolp[(bh * 2 + 1) * 64 + tid]) / (*cntp);

    // softmax over 196 masked logits
    const float bsp = bsg[0];
    float lv = -1e30f;
    if (tid < Mm) lv = (maskv[tid] == 0.f) ? -1e9f : (logits[tid] + bsp);

    float v = lv;
    #pragma unroll
    for (int off = 16; off > 0; off >>= 1) v = fmaxf(v, __shfl_xor_sync(0xffffffffu, v, off));
    if (lane == 0) red[wid] = v;
    __syncthreads();
    float mx = red[0];
    #pragma unroll
    for (int i = 1; i < 16; ++i) mx = fmaxf(mx, red[i]);
    __syncthreads();

    float w = 0.f;
    if (tid < Mm) { w = __expf(lv - mx); wts[tid] = w; }
    float sw = w;
    #pragma unroll
    for (int off = 16; off > 0; off >>= 1) sw += __shfl_xor_sync(0xffffffffu, sw, off);
    if (lane == 0) red[wid] = sw;
    __syncthreads();
    float Z = 0.f;
    #pragma unroll
    for (int i = 0; i < 16; ++i) Z += red[i];
    __syncthreads();

    // v2 = sum_m alpha[m] * value2[m, :]
    const int grp = tid >> 7;   // 0..3
    const int vv = tid & 127;
    const float* v2row = v2g_all + (size_t)bh * Mm * 128;
    float a = 0.f;
    #pragma unroll 4
    for (int m = grp; m < Mm; m += 4) a += wts[m] * v2row[m * 128 + vv];
    v2p[grp * 128 + vv] = a;
    __syncthreads();

    if (tid < 128) {
        float v2v = (v2p[vv] + v2p[128 + vv] + v2p[256 + vv] + v2p[384 + vv]) / Z;
        float s = 0.f;
        #pragma unroll 8
        for (int e = 0; e < 64; ++e) s += pool[e] * Wcg[e * 128 + vv];
        float ac = 1.f / (1.f + __expf(-(s + bcg[vv])));
        outg[bh * 128 + vv] = v1g[bh * 128 + vv] * v2v * ac;
    }
}

extern "C" void kernel_launch(void* const* d_in, const int* in_sizes, int n_in,
                              void* d_out, int out_size) {
    const float* q   = (const float*)d_in[0];
    const float* key = (const float*)d_in[1];
    const float* msk = (const float*)d_in[2];
    const float* v1  = (const float*)d_in[3];
    const float* v2  = (const float*)d_in[4];
    const float* Wb  = (const float*)d_in[5];
    const float* bb  = (const float*)d_in[6];
    const float* Ws  = (const float*)d_in[7];
    const float* bs  = (const float*)d_in[8];
    const float* Wc  = (const float*)d_in[9];
    const float* bc  = (const float*)d_in[10];
    float* out = (float*)d_out;

    cudaFuncSetAttribute(k1_gemm, cudaFuncAttributeMaxDynamicSharedMemorySize, (int)K1_SMEM);
    k1_gemm<<<2048, 256, K1_SMEM>>>(q, key, msk, Wb, bb, Ws);
    k2_final<<<1024, 512, K2_SMEM>>>(msk, v1, v2, bs, Wc, bc, out);
}

// round 6
// speedup vs baseline: 2.0728x; 1.0961x over previous
#include <cuda_runtime.h>
#include <cuda_fp16.h>
#include <cstdint>

#define Mm 196

// ---- kernel1 smem offsets ----
#define K1_B      0u        // 8*8*32*16 = 32768 (B fragments)
#define K1_QS     32768u    // 128 f
#define K1_WS     33280u    // 64 f
#define K1_BB     33536u    // 64 f
#define K1_MASK   33792u    // 256 f zero-padded
#define K1_POOLP  34816u    // 8*64 f
#define K1_SMEM   36864u

// ---- kernel2 smem offsets ----
#define K2_MASK   0u        // 256 f
#define K2_LOG    1024u     // 256 f
#define K2_WTS    2048u     // 256 f
#define K2_POOL   3072u     // 64 f
#define K2_V2P    3328u     // 16*128 f = 8192
#define K2_RED    11520u    // 16 f
#define K2_CNT    11584u
#define K2_SMEM   11648u

__device__ float g_logits[1024 * 196];
__device__ float g_poolp[2048 * 64];

__device__ __forceinline__ void split2(float x, float y, uint32_t& hi, uint32_t& lo) {
    __half hx = __float2half_rn(x), hy = __float2half_rn(y);
    __half lx = __float2half_rn(x - __half2float(hx));
    __half ly = __float2half_rn(y - __half2float(hy));
    hi = ((uint32_t)__half_as_ushort(hy) << 16) | (uint32_t)__half_as_ushort(hx);
    lo = ((uint32_t)__half_as_ushort(ly) << 16) | (uint32_t)__half_as_ushort(lx);
}

__device__ __forceinline__ void mma16816(float* d, uint32_t a0, uint32_t a1, uint32_t a2,
                                         uint32_t a3, uint32_t b0, uint32_t b1) {
    asm volatile(
        "mma.sync.aligned.m16n8k16.row.col.f32.f16.f16.f32 "
        "{%0,%1,%2,%3}, {%4,%5,%6,%7}, {%8,%9}, {%0,%1,%2,%3};"
        : "+f"(d[0]), "+f"(d[1]), "+f"(d[2]), "+f"(d[3])
        : "r"(a0), "r"(a1), "r"(a2), "r"(a3), "r"(b0), "r"(b1));
}

__device__ __forceinline__ void lds128(uint32_t& x, uint32_t& y, uint32_t& z, uint32_t& w,
                                       uint32_t addr) {
    asm volatile("ld.shared.v4.b32 {%0,%1,%2,%3}, [%4];"
                 : "=r"(x), "=r"(y), "=r"(z), "=r"(w) : "r"(addr));
}

// ================= kernel 1: fused GEMM + logits/pool partials =================
// k-permutation: inside each 16-k group, thread t's fragment covers PHYSICAL
// cols 4t..4t+3 (one float4). b0 pairs cols (4t,4t+1), b1 pairs (4t+2,4t+3).
__global__ __launch_bounds__(256, 2)
void k1_gemm(const float* __restrict__ qg, const float* __restrict__ keyg_all,
             const float* __restrict__ maskg, const float* __restrict__ Wbg,
             const float* __restrict__ bbg, const float* __restrict__ Wsg)
{
    extern __shared__ char sm[];
    const uint32_t smb = (uint32_t)__cvta_generic_to_shared(sm);
    const int tid = threadIdx.x;
    const int lane = tid & 31;
    const int wid = tid >> 5;
    const int bid = blockIdx.x;
    const int bh = bid >> 1;
    const int half = bid & 1;
    const int b = bh >> 3;
    const int m0 = half * 112;
    const int ntiles = half ? 6 : 7;

    float* qs    = (float*)(sm + K1_QS);
    float* wss   = (float*)(sm + K1_WS);
    float* bbs   = (float*)(sm + K1_BB);
    float* maskv = (float*)(sm + K1_MASK);
    float* poolp = (float*)(sm + K1_POOLP);

    // phase 0
    if (tid < 128) qs[tid] = qg[bh * 128 + tid];
    if (tid < 64) { wss[tid] = Wsg[tid]; bbs[tid] = bbg[tid]; }
    maskv[tid] = (tid < Mm) ? maskg[b * Mm + tid] : 0.f;
    __syncthreads();

    // pack B fragments straight from global (L2-hot): Wq[k][e] = q[k]*Wb[k][e]
    #pragma unroll
    for (int task = tid; task < 512; task += 256) {
        const int e = task & 63;
        const int ks = task >> 6;
        const int nt = e >> 3;
        const uint32_t slotbase = (uint32_t)((nt * 8 + ks) * 32);
        #pragma unroll
        for (int t = 0; t < 4; ++t) {
            const int c = ks * 16 + t * 4;
            const float x0 = Wbg[c * 64 + e] * qs[c];
            const float x1 = Wbg[(c + 1) * 64 + e] * qs[c + 1];
            const float x2 = Wbg[(c + 2) * 64 + e] * qs[c + 2];
            const float x3 = Wbg[(c + 3) * 64 + e] * qs[c + 3];
            uint32_t b0h, b0l, b1h, b1l;
            split2(x0, x1, b0h, b0l);
            split2(x2, x3, b1h, b1l);
            const int ln = 4 * (e & 7) + t;
            uint4 val; val.x = b0h; val.y = b1h; val.z = b0l; val.w = b1l;
            *(uint4*)(sm + K1_B + (slotbase + ln) * 16) = val;
        }
    }
    __syncthreads();

    if (wid < ntiles) {
        float acc[8][4];
        #pragma unroll
        for (int nt = 0; nt < 8; ++nt)
            #pragma unroll
            for (int r = 0; r < 4; ++r) acc[nt][r] = 0.f;

        const float* keyg = keyg_all + (size_t)bh * Mm * 128;
        const int g = lane >> 2, t = lane & 3;
        const int r0 = m0 + wid * 16 + g;
        const int r1 = r0 + 8;
        const int r0c = (r0 < Mm) ? r0 : (Mm - 1);
        const int r1c = (r1 < Mm) ? r1 : (Mm - 1);
        const float4* p0 = (const float4*)(keyg + r0c * 128) + t;
        const float4* p1 = (const float4*)(keyg + r1c * 128) + t;

        // load entire row pair up front: 16 independent LDG.128
        float4 A0[8], A1[8];
        #pragma unroll
        for (int ks = 0; ks < 8; ++ks) A0[ks] = p0[ks * 4];
        #pragma unroll
        for (int ks = 0; ks < 8; ++ks) A1[ks] = p1[ks * 4];

        #pragma unroll
        for (int ks = 0; ks < 8; ++ks) {
            uint32_t a0h, a0l, a1h, a1l, a2h, a2l, a3h, a3l;
            split2(A0[ks].x, A0[ks].y, a0h, a0l);
            split2(A1[ks].x, A1[ks].y, a1h, a1l);
            split2(A0[ks].z, A0[ks].w, a2h, a2l);
            split2(A1[ks].z, A1[ks].w, a3h, a3l);
            #pragma unroll
            for (int nt = 0; nt < 8; ++nt) {
                uint32_t b0h, b1h, b0l, b1l;
                lds128(b0h, b1h, b0l, b1l,
                       smb + K1_B + (uint32_t)((nt * 8 + ks) * 32 + lane) * 16);
                mma16816(acc[nt], a0h, a1h, a2h, a3h, b0h, b1h);
                mma16816(acc[nt], a0h, a1h, a2h, a3h, b0l, b1l);
                mma16816(acc[nt], a0l, a1l, a2l, a3l, b0h, b1h);
            }
        }

        // epilogue: relu+bias -> logit rows + masked pool partials
        const float mk0 = maskv[r0 < 256 ? r0 : 255];
        const float mk1 = maskv[r1 < 256 ? r1 : 255];
        float lp0 = 0.f, lp1 = 0.f;
        #pragma unroll
        for (int nt = 0; nt < 8; ++nt) {
            const int e0 = nt * 8 + t * 2;
            const float ba = bbs[e0], bbv = bbs[e0 + 1];
            const float wa = wss[e0], wbv = wss[e0 + 1];
            float h0 = fmaxf(acc[nt][0] + ba, 0.f);
            float h1 = fmaxf(acc[nt][1] + bbv, 0.f);
            float h2 = fmaxf(acc[nt][2] + ba, 0.f);
            float h3 = fmaxf(acc[nt][3] + bbv, 0.f);
            lp0 += h0 * wa + h1 * wbv;
            lp1 += h2 * wa + h3 * wbv;
            float pva = mk0 * h0 + mk1 * h2;
            float pvb = mk0 * h1 + mk1 * h3;
            pva += __shfl_xor_sync(0xffffffffu, pva, 4);
            pva += __shfl_xor_sync(0xffffffffu, pva, 8);
            pva += __shfl_xor_sync(0xffffffffu, pva, 16);
            pvb += __shfl_xor_sync(0xffffffffu, pvb, 4);
            pvb += __shfl_xor_sync(0xffffffffu, pvb, 8);
            pvb += __shfl_xor_sync(0xffffffffu, pvb, 16);
            if (g == 0) {
                poolp[wid * 64 + e0] = pva;
                poolp[wid * 64 + e0 + 1] = pvb;
            }
        }
        lp0 += __shfl_xor_sync(0xffffffffu, lp0, 1);
        lp0 += __shfl_xor_sync(0xffffffffu, lp0, 2);
        lp1 += __shfl_xor_sync(0xffffffffu, lp1, 1);
        lp1 += __shfl_xor_sync(0xffffffffu, lp1, 2);
        if (t == 0) {
            if (r0 < Mm) g_logits[bh * Mm + r0] = lp0;
            if (r1 < Mm) g_logits[bh * Mm + r1] = lp1;
        }
    }
    __syncthreads();

    if (tid < 64) {
        float s = 0.f;
        for (int w = 0; w < ntiles; ++w) s += poolp[w * 64 + tid];
        g_poolp[bid * 64 + tid] = s;
    }
}

// ================= kernel 2: softmax + v2 stream + gate =================
__global__ __launch_bounds__(512)
void k2_final(const float* __restrict__ maskg, const float* __restrict__ v1g,
              const float* __restrict__ v2g_all, const float* __restrict__ bsg,
              const float* __restrict__ Wcg, const float* __restrict__ bcg,
              float* __restrict__ outg)
{
    extern __shared__ char sm[];
    const int tid = threadIdx.x;
    const int lane = tid & 31;
    const int wid = tid >> 5;
    const int bh = blockIdx.x;
    const int b = bh >> 3;

    float* maskv  = (float*)(sm + K2_MASK);
    float* logits = (float*)(sm + K2_LOG);
    float* wts    = (float*)(sm + K2_WTS);
    float* pool   = (float*)(sm + K2_POOL);
    float* v2p    = (float*)(sm + K2_V2P);
    float* red    = (float*)(sm + K2_RED);
    float* cntp   = (float*)(sm + K2_CNT);

    if (tid == 0) *cntp = 0.f;
    __syncthreads();

    if (tid < 256) {
        float mv = (tid < Mm) ? maskg[b * Mm + tid] : 0.f;
        maskv[tid] = mv;
        if (tid < Mm) {
            logits[tid] = g_logits[bh * Mm + tid];
            atomicAdd(cntp, mv);
        }
    }
    __syncthreads();

    if (tid < 64)
        pool[tid] = (g_poolp[(bh * 2) * 64 + tid] + g_poolp[(bh * 2 + 1) * 64 + tid]) / (*cntp);

    // softmax over 196 masked logits
    const float bsp = bsg[0];
    float lv = -1e30f;
    if (tid < Mm) lv = (maskv[tid] == 0.f) ? -1e9f : (logits[tid] + bsp);

    float v = lv;
    #pragma unroll
    for (int off = 16; off > 0; off >>= 1) v = fmaxf(v, __shfl_xor_sync(0xffffffffu, v, off));
    if (lane == 0) red[wid] = v;
    __syncthreads();
    float mx = red[0];
    #pragma unroll
    for (int i = 1; i < 16; ++i) mx = fmaxf(mx, red[i]);
    __syncthreads();

    float w = 0.f;
    if (tid < Mm) { w = __expf(lv - mx); wts[tid] = w; }
    float sw = w;
    #pragma unroll
    for (int off = 16; off > 0; off >>= 1) sw += __shfl_xor_sync(0xffffffffu, sw, off);
    if (lane == 0) red[wid] = sw;
    __syncthreads();
    float Z = 0.f;
    #pragma unroll
    for (int i = 0; i < 16; ++i) Z += red[i];
    __syncthreads();

    // v2 = sum_m alpha[m] * value2[m, :]  — warp w owns rows m ≡ w (mod 16)
    {
        const float4* v2r = (const float4*)(v2g_all + (size_t)bh * Mm * 128);
        float4 a4 = make_float4(0.f, 0.f, 0.f, 0.f);
        #pragma unroll
        for (int i = 0; i < 13; ++i) {
            const int m = wid + 16 * i;
            if (m < Mm) {
                const float wt = wts[m];
                const float4 vv4 = v2r[m * 32 + lane];
                a4.x += wt * vv4.x;
                a4.y += wt * vv4.y;
                a4.z += wt * vv4.z;
                a4.w += wt * vv4.w;
            }
        }
        ((float4*)v2p)[wid * 32 + lane] = a4;
    }
    __syncthreads();

    if (tid < 128) {
        const int vv = tid;
        float v2v = 0.f;
        #pragma unroll
        for (int g = 0; g < 16; ++g) v2v += v2p[g * 128 + vv];
        v2v /= Z;
        float s = 0.f;
        #pragma unroll 8
        for (int e = 0; e < 64; ++e) s += pool[e] * Wcg[e * 128 + vv];
        float ac = 1.f / (1.f + __expf(-(s + bcg[vv])));
        outg[bh * 128 + vv] = v1g[bh * 128 + vv] * v2v * ac;
    }
}

extern "C" void kernel_launch(void* const* d_in, const int* in_sizes, int n_in,
                              void* d_out, int out_size) {
    const float* q   = (const float*)d_in[0];
    const float* key = (const float*)d_in[1];
    const float* msk = (const float*)d_in[2];
    const float* v1  = (const float*)d_in[3];
    const float* v2  = (const float*)d_in[4];
    const float* Wb  = (const float*)d_in[5];
    const float* bb  = (const float*)d_in[6];
    const float* Ws  = (const float*)d_in[7];
    const float* bs  = (const float*)d_in[8];
    const float* Wc  = (const float*)d_in[9];
    const float* bc  = (const float*)d_in[10];
    float* out = (float*)d_out;

    cudaFuncSetAttribute(k1_gemm, cudaFuncAttributeMaxDynamicSharedMemorySize, (int)K1_SMEM);
    k1_gemm<<<2048, 256, K1_SMEM>>>(q, key, msk, Wb, bb, Ws);
    k2_final<<<1024, 512, K2_SMEM>>>(msk, v1, v2, bs, Wc, bc, out);
}